// round 14
// baseline (speedup 1.0000x reference)
#include <cuda_runtime.h>

#define BB 8192
#define MM 16
#define NN 256
#define CC 64
#define NBLK 296
#define NTILES 2048   /* (BB/64) * MM */

#define SCB 256   /* codebook row stride in float2 (16B-aligned rows; cv loads are broadcast) */
#define SXS 65    /* x-tile  row stride in float2 */

typedef unsigned long long ull;
typedef unsigned int uint;

// Packed fp32x2 FMA (Blackwell sm_103a; only reachable via PTX)
__device__ __forceinline__ void ffma2(ull &d, ull a, ull b) {
    asm("fma.rn.f32x2 %0, %1, %2, %0;" : "+l"(d) : "l"(a), "l"(b));
}

// Order-preserving float -> uint (unsigned compare == float compare)
__device__ __forceinline__ uint fenc(float f) {
    uint b = __float_as_uint(f);
    return (b & 0x80000000u) ? ~b : (b | 0x80000000u);
}

__global__ __launch_bounds__(512, 1)
void fq_kernel(const float* __restrict__ inp, const float* __restrict__ cb,
               float* __restrict__ codes, float* __restrict__ idx_out, int write_idx)
{
    extern __shared__ float2 sm2[];
    float2* cbp = sm2;                          // [32][SCB] codebook pairs: cbp[cp][n]
    float2* xsp = sm2 + 32 * SCB;               // [32][SXS] x pairs:        xsp[cp][row]
    float*  c2s = (float*)(xsp + 32 * SXS);     // [256] ||c||^2
    ull*    red = (ull*)(c2s + NN);             // [16][64] per-warp packed argmin partials
    int*    bnS = (int*)(red + 16 * 64);        // [64] final argmin per row

    const int tid  = threadIdx.x;
    const int w    = tid >> 5;                  // warp 0..15: owns cols w*16 .. +15
    const int lane = tid & 31;                  // owns rows lane, lane+32
    const int colb = w * 16;

    const int t0 = (int)(((long long)blockIdx.x       * NTILES) / NBLK);
    const int t1 = (int)(((long long)(blockIdx.x + 1) * NTILES) / NBLK);

    int prev_m = -1;
    for (int t = t0; t < t1; t++) {
        const int m     = t >> 7;
        const int chunk = t & 127;

        if (m != prev_m) {
            __syncthreads();   // previous tile's reads of cbp/c2s complete
            // Load codebook[m] (16384 floats = 4096 float4) coalesced; store pair-transposed.
            const float4* cg = (const float4*)(cb + (size_t)m * NN * CC);
            #pragma unroll
            for (int k = 0; k < 8; k++) {
                int i4 = tid + k * 512;
                float4 v = cg[i4];
                int n  = i4 >> 4;                  // element/64
                int cp = ((i4 * 4) & 63) >> 1;     // even pair index
                cbp[cp * SCB + n]       = make_float2(v.x, v.y);
                cbp[(cp + 1) * SCB + n] = make_float2(v.z, v.w);
            }
            __syncthreads();
            if (tid < NN) {   // ||c||^2 per codeword (lane-contiguous, CF)
                float s = 0.f;
                #pragma unroll
                for (int cp = 0; cp < 32; cp++) {
                    float2 p = cbp[cp * SCB + tid];
                    s = fmaf(p.x, p.x, fmaf(p.y, p.y, s));
                }
                c2s[tid] = s;
            }
            prev_m = m;
        }

        __syncthreads();   // prior tile fully consumed before overwriting xsp
        {   // Load x tile: 64 rows x 64 floats; 8 threads/row, 8 floats (2 float4) each.
            int row = tid >> 3;              // 0..63
            int c0  = (tid & 7) * 8;
            const float* xg = inp + ((size_t)(chunk * 64 + row) * MM + m) * CC + c0;
            int cp0 = c0 >> 1;
            #pragma unroll
            for (int q = 0; q < 2; q++) {
                float4 v = *(const float4*)(xg + q * 4);
                xsp[(cp0 + 2 * q) * SXS + row]     = make_float2(v.x, v.y);
                xsp[(cp0 + 2 * q + 1) * SXS + row] = make_float2(v.z, v.w);
            }
        }
        __syncthreads();

        // Accumulate: 2 rows x 16 cols per thread, f32x2 packed over (even c, odd c).
        ull acc0[16], acc1[16];
        #pragma unroll
        for (int j = 0; j < 16; j++) { acc0[j] = 0ull; acc1[j] = 0ull; }

        const ull* xr = (const ull*)xsp;

        #pragma unroll 2
        for (int cp = 0; cp < 32; cp++) {
            ull x0 = xr[cp * SXS + lane];            // LDS.64, 32 lanes contiguous, CF
            ull x1 = xr[cp * SXS + lane + 32];
            const ulonglong2* cq = (const ulonglong2*)(cbp + cp * SCB) + w * 8;
            #pragma unroll
            for (int jq = 0; jq < 8; jq++) {
                ulonglong2 q = cq[jq];               // LDS.128 broadcast (all lanes same addr)
                ffma2(acc0[2 * jq],     x0, q.x);
                ffma2(acc0[2 * jq + 1], x0, q.y);
                ffma2(acc1[2 * jq],     x1, q.x);
                ffma2(acc1[2 * jq + 1], x1, q.y);
            }
        }

        // Per-thread argmin over its 16 cols; dist = ||c||^2 - 2*dot (x^2 invariant).
        // Packed key: (monotone(dist) << 32) | col  -> unsigned min == (min dist, first col).
        ull bp0 = ~0ull, bp1 = ~0ull;
        #pragma unroll
        for (int j = 0; j < 16; j++) {
            uint col = colb + j;
            float c2 = c2s[col];                      // broadcast
            float2 p0 = *(float2*)&acc0[j];
            float2 p1 = *(float2*)&acc1[j];
            float d0 = fmaf(-2.f, p0.x + p0.y, c2);
            float d1 = fmaf(-2.f, p1.x + p1.y, c2);
            ull k0 = ((ull)fenc(d0) << 32) | col;
            ull k1 = ((ull)fenc(d1) << 32) | col;
            if (k0 < bp0) bp0 = k0;
            if (k1 < bp1) bp1 = k1;
        }
        red[w * 64 + lane]      = bp0;
        red[w * 64 + lane + 32] = bp1;
        __syncthreads();

        const size_t b0 = (size_t)chunk * 64;
        if (tid < 64) {   // reduce 16 warp-partials per row
            ull best = red[tid];
            #pragma unroll
            for (int w2 = 1; w2 < 16; w2++) {
                ull v = red[w2 * 64 + tid];
                if (v < best) best = v;
            }
            int n = (int)(best & 0xFFFFFFFFull);
            bnS[tid] = n;
            if (write_idx) idx_out[(b0 + tid) * MM + m] = (float)n;
        }
        __syncthreads();

        // Gather codes from global codebook (L2-hot); warp w handles rows 4w..4w+3.
        #pragma unroll
        for (int i = 0; i < 4; i++) {
            int r = w * 4 + i;
            int n = bnS[r];
            const float2* src = (const float2*)(cb + ((size_t)m * NN + n) * CC);
            float2 v = __ldg(src + lane);
            ((float2*)(codes + ((b0 + r) * MM + m) * CC))[lane] = v;
        }
    }
}

extern "C" void kernel_launch(void* const* d_in, const int* in_sizes, int n_in,
                              void* d_out, int out_size) {
    const float* inp = (const float*)d_in[0];   // [B, M, C] f32
    const float* cb  = (const float*)d_in[1];   // [M, N, C] f32
    float* codes = (float*)d_out;
    float* idx_o = (float*)d_out + (size_t)BB * MM * CC;
    const int write_idx = (out_size >= BB * MM * CC + BB * MM) ? 1 : 0;

    const int smem_bytes = (32 * SCB + 32 * SXS) * 8 + NN * 4 + 16 * 64 * 8 + 64 * 4; // 91904
    cudaFuncSetAttribute(fq_kernel, cudaFuncAttributeMaxDynamicSharedMemorySize, smem_bytes);
    fq_kernel<<<NBLK, 512, smem_bytes>>>(inp, cb, codes, idx_o, write_idx);
}

// round 17
// speedup vs baseline: 1.5303x; 1.5303x over previous
#include <cuda_runtime.h>
#include <cuda_bf16.h>
#include <cstdint>

#define BB 8192
#define MM 16
#define NN 256
#define CC 64
#define ROWS 128
#define NBLK 148
#define NTILES 1024          /* (BB/ROWS) * MM */
#define CBF_S 66
#define XF_S  66
#define MARGIN 0.02f

/* smem byte offsets (bf16 tiles 1024-aligned; rows = 128B, SW128-swizzled) */
#define OFF_XH    0
#define OFF_XL    16384
#define OFF_CBH   32768
#define OFF_CBL   65536
#define OFF_CBF   98304                    /* 256*66*4 = 67584 */
#define OFF_XF    (OFF_CBF + 67584)        /* 128*66*4 = 33792 */
#define OFF_C2    (OFF_XF + 33792)         /* 256*4 -> pad 1024 */
#define OFF_RED   (OFF_C2 + 1024)          /* 128 * 16 */
#define OFF_BNS   (OFF_RED + 2048)         /* 128 * 4 -> pad 512 */
#define SMEM_TOTAL (OFF_BNS + 512)         /* 203264 */

#define SW(o) ((o) ^ (((o) >> 3) & 0x70))

typedef unsigned long long ull;
typedef unsigned int uint;

__device__ __forceinline__ uint smem_u32(const void* p) {
    uint a;
    asm("{ .reg .u64 t; cvta.to.shared.u64 t, %1; cvt.u32.u64 %0, t; }" : "=r"(a) : "l"(p));
    return a;
}
__device__ __forceinline__ void ldsm4(uint* r, uint addr) {
    asm volatile("ldmatrix.sync.aligned.m8n8.x4.shared.b16 {%0,%1,%2,%3}, [%4];"
                 : "=r"(r[0]), "=r"(r[1]), "=r"(r[2]), "=r"(r[3]) : "r"(addr));
}
__device__ __forceinline__ void mma_bf16(float* c, const uint* a, const uint* b) {
    asm volatile("mma.sync.aligned.m16n8k16.row.col.f32.bf16.bf16.f32 "
                 "{%0,%1,%2,%3}, {%4,%5,%6,%7}, {%8,%9}, {%0,%1,%2,%3};"
                 : "+f"(c[0]), "+f"(c[1]), "+f"(c[2]), "+f"(c[3])
                 : "r"(a[0]), "r"(a[1]), "r"(a[2]), "r"(a[3]), "r"(b[0]), "r"(b[1]));
}
__device__ __forceinline__ uint fenc(float f) {
    uint b = __float_as_uint(f);
    return (b & 0x80000000u) ? ~b : (b | 0x80000000u);
}
__device__ __forceinline__ float fdec(uint u) {
    return (u & 0x80000000u) ? __uint_as_float(u & 0x7fffffffu) : __uint_as_float(~u);
}
__device__ __forceinline__ void merge2(ull &k1, ull &k2, ull nk) {
    if (nk < k1) { k2 = k1; k1 = nk; } else if (nk < k2) { k2 = nk; }
}

__global__ __launch_bounds__(256, 1)
void fq_mma_kernel(const float* __restrict__ inp, const float* __restrict__ cb,
                   float* __restrict__ codes, float* __restrict__ idx_out, int write_idx)
{
    extern __shared__ char smem[];
    const uint sb = smem_u32(smem);
    float* CBf = (float*)(smem + OFF_CBF);
    float* Xf  = (float*)(smem + OFF_XF);
    float* c2s = (float*)(smem + OFF_C2);
    ulonglong2* red = (ulonglong2*)(smem + OFF_RED);
    int* bnS = (int*)(smem + OFF_BNS);

    const int tid  = threadIdx.x;
    const int w    = tid >> 5;               /* warp w: rows w*16 .. +15 */
    const int lane = tid & 31;

    /* per-lane ldmatrix address components */
    const int arow  = w * 16 + (lane & 15);
    const int akoff = ((lane >> 4) & 1) * 16;
    const int bn_   = (lane & 7) + ((lane >> 4) & 1) * 8;
    const int bkoff = ((lane >> 3) & 1) * 16;

    const int t0 = (int)(((long long)blockIdx.x       * NTILES) / NBLK);
    const int t1 = (int)(((long long)(blockIdx.x + 1) * NTILES) / NBLK);

    int prev_m = -1;
    for (int t = t0; t < t1; t++) {
        const int m     = t >> 6;
        const int chunk = t & 63;
        const size_t b0 = (size_t)chunk * ROWS;

        if (m != prev_m) {
            __syncthreads();   /* prior epilogue done reading CBf/c2s */
            const float4* cg = (const float4*)(cb + (size_t)m * NN * CC);
            #pragma unroll
            for (int k = 0; k < 16; k++) {
                int f = tid + k * 256;
                float4 v = cg[f];
                int n = f >> 4, q = f & 15;
                *(float2*)(CBf + n * CBF_S + q * 4)     = make_float2(v.x, v.y);
                *(float2*)(CBf + n * CBF_S + q * 4 + 2) = make_float2(v.z, v.w);
                __nv_bfloat16 h0 = __float2bfloat16_rn(v.x), h1 = __float2bfloat16_rn(v.y);
                __nv_bfloat16 h2 = __float2bfloat16_rn(v.z), h3 = __float2bfloat16_rn(v.w);
                __nv_bfloat16 l0 = __float2bfloat16_rn(v.x - __bfloat162float(h0));
                __nv_bfloat16 l1 = __float2bfloat16_rn(v.y - __bfloat162float(h1));
                __nv_bfloat16 l2 = __float2bfloat16_rn(v.z - __bfloat162float(h2));
                __nv_bfloat16 l3 = __float2bfloat16_rn(v.w - __bfloat162float(h3));
                uint o0 = SW(n * 128 + q * 8), o1 = SW(n * 128 + q * 8 + 4);
                *(__nv_bfloat162*)(smem + OFF_CBH + o0) = __nv_bfloat162(h0, h1);
                *(__nv_bfloat162*)(smem + OFF_CBH + o1) = __nv_bfloat162(h2, h3);
                *(__nv_bfloat162*)(smem + OFF_CBL + o0) = __nv_bfloat162(l0, l1);
                *(__nv_bfloat162*)(smem + OFF_CBL + o1) = __nv_bfloat162(l2, l3);
            }
            __syncthreads();
            {   /* exact fp32 ||c||^2 (same values used in both argmin passes) */
                float s = 0.f;
                const float* p = CBf + tid * CBF_S;
                #pragma unroll
                for (int c = 0; c < CC; c++) s = fmaf(p[c], p[c], s);
                c2s[tid] = s;
            }
            prev_m = m;
        }

        __syncthreads();   /* prior tile fully consumed before overwriting X */
        #pragma unroll
        for (int k = 0; k < 8; k++) {
            int f = tid + k * 256;
            int r = f >> 4, q = f & 15;
            float4 v = *(const float4*)(inp + ((b0 + r) * MM + m) * CC + q * 4);
            *(float2*)(Xf + r * XF_S + q * 4)     = make_float2(v.x, v.y);
            *(float2*)(Xf + r * XF_S + q * 4 + 2) = make_float2(v.z, v.w);
            __nv_bfloat16 h0 = __float2bfloat16_rn(v.x), h1 = __float2bfloat16_rn(v.y);
            __nv_bfloat16 h2 = __float2bfloat16_rn(v.z), h3 = __float2bfloat16_rn(v.w);
            __nv_bfloat16 l0 = __float2bfloat16_rn(v.x - __bfloat162float(h0));
            __nv_bfloat16 l1 = __float2bfloat16_rn(v.y - __bfloat162float(h1));
            __nv_bfloat16 l2 = __float2bfloat16_rn(v.z - __bfloat162float(h2));
            __nv_bfloat16 l3 = __float2bfloat16_rn(v.w - __bfloat162float(h3));
            uint o0 = SW(r * 128 + q * 8), o1 = SW(r * 128 + q * 8 + 4);
            *(__nv_bfloat162*)(smem + OFF_XH + o0) = __nv_bfloat162(h0, h1);
            *(__nv_bfloat162*)(smem + OFF_XH + o1) = __nv_bfloat162(h2, h3);
            *(__nv_bfloat162*)(smem + OFF_XL + o0) = __nv_bfloat162(l0, l1);
            *(__nv_bfloat162*)(smem + OFF_XL + o1) = __nv_bfloat162(l2, l3);
        }
        __syncthreads();

        /* ---- MMA mainloop: 3-term bf16 split (hh + hl + lh), fp32 accum ---- */
        float acc[32][4];
        #pragma unroll
        for (int nt = 0; nt < 32; nt++)
            #pragma unroll
            for (int q = 0; q < 4; q++) acc[nt][q] = 0.f;

        #pragma unroll
        for (int ks = 0; ks < 4; ks++) {
            uint ah[4], al[4];
            uint ao = SW(arow * 128 + ks * 32 + akoff);
            ldsm4(ah, sb + OFF_XH + ao);
            ldsm4(al, sb + OFF_XL + ao);
            #pragma unroll
            for (int g = 0; g < 16; g++) {   /* 2 n-tiles per ldmatrix.x4 */
                uint bh[4], bl[4];
                uint bo = SW((g * 16 + bn_) * 128 + ks * 32 + bkoff);
                ldsm4(bh, sb + OFF_CBH + bo);
                ldsm4(bl, sb + OFF_CBL + bo);
                mma_bf16(acc[g * 2],     ah, bh);
                mma_bf16(acc[g * 2],     al, bh);
                mma_bf16(acc[g * 2],     ah, bl);
                mma_bf16(acc[g * 2 + 1], ah, bh + 2);
                mma_bf16(acc[g * 2 + 1], al, bh + 2);
                mma_bf16(acc[g * 2 + 1], ah, bl + 2);
            }
        }

        /* ---- approx argmin with runner-up tracking (packed keys) ---- */
        /* thread holds rows rA = w*16 + lane/4 and rB = rA+8; cols nt*8 + 2*(lane&3) +{0,1} */
        ull k1A = ~0ull, k2A = ~0ull, k1B = ~0ull, k2B = ~0ull;
        #pragma unroll
        for (int nt = 0; nt < 32; nt++) {
            uint c0 = nt * 8 + 2 * (lane & 3);
            float c2a = c2s[c0], c2b = c2s[c0 + 1];
            merge2(k1A, k2A, ((ull)fenc(fmaf(-2.f, acc[nt][0], c2a)) << 32) | c0);
            merge2(k1A, k2A, ((ull)fenc(fmaf(-2.f, acc[nt][1], c2b)) << 32) | (c0 + 1));
            merge2(k1B, k2B, ((ull)fenc(fmaf(-2.f, acc[nt][2], c2a)) << 32) | c0);
            merge2(k1B, k2B, ((ull)fenc(fmaf(-2.f, acc[nt][3], c2b)) << 32) | (c0 + 1));
        }
        #pragma unroll
        for (int o = 1; o <= 2; o <<= 1) {
            ull a1 = __shfl_xor_sync(0xffffffffu, k1A, o);
            ull a2 = __shfl_xor_sync(0xffffffffu, k2A, o);
            merge2(k1A, k2A, a1); merge2(k1A, k2A, a2);
            ull b1 = __shfl_xor_sync(0xffffffffu, k1B, o);
            ull b2 = __shfl_xor_sync(0xffffffffu, k2B, o);
            merge2(k1B, k2B, b1); merge2(k1B, k2B, b2);
        }
        if ((lane & 3) == 0) {
            int rA = w * 16 + (lane >> 2);
            red[rA]     = make_ulonglong2(k1A, k2A);
            red[rA + 8] = make_ulonglong2(k1B, k2B);
        }
        __syncthreads();

        /* ---- certify; rare exact fp32 rescore for ambiguous rows ---- */
        if (tid < 128) {
            ulonglong2 kk = red[tid];
            uint n1 = (uint)(kk.x & 0xffffffffull);
            float d1 = fdec((uint)(kk.x >> 32));
            float d2 = fdec((uint)(kk.y >> 32));
            bool flag = (d2 <= d1 + MARGIN);
            bnS[tid] = (int)n1;
            uint fl = __ballot_sync(0xffffffffu, flag);
            while (fl) {
                int f = __ffs(fl) - 1; fl &= fl - 1;
                int rr = (tid & ~31) | f;
                const float* xr = Xf + rr * XF_S;
                ull bk = ~0ull;
                for (int i = 0; i < 8; i++) {
                    int col = lane + 32 * i;
                    const float* cr = CBf + col * CBF_S;
                    float s = 0.f;
                    #pragma unroll
                    for (int c = 0; c < CC; c++) s = fmaf(xr[c], cr[c], s);
                    float d = fmaf(-2.f, s, c2s[col]);
                    ull k = ((ull)fenc(d) << 32) | (uint)col;
                    if (k < bk) bk = k;
                }
                #pragma unroll
                for (int o = 16; o; o >>= 1) {
                    ull ok = __shfl_xor_sync(0xffffffffu, bk, o);
                    if (ok < bk) bk = ok;
                }
                if (lane == 0) bnS[rr] = (int)(bk & 0xffffffffull);
            }
        }
        __syncthreads();

        if (write_idx && tid < 128)
            idx_out[(b0 + tid) * MM + m] = (float)bnS[tid];

        /* ---- gather codes (smem fp32 codebook), coalesced float2 writes ---- */
        #pragma unroll
        for (int i = 0; i < 16; i++) {
            int row = w * 16 + i;
            int n = bnS[row];
            float2 v = *(float2*)(CBf + n * CBF_S + 2 * lane);
            *(float2*)(codes + ((b0 + row) * MM + m) * CC + 2 * lane) = v;
        }
    }
}

extern "C" void kernel_launch(void* const* d_in, const int* in_sizes, int n_in,
                              void* d_out, int out_size) {
    const float* inp = (const float*)d_in[0];   // [B, M, C] f32
    const float* cb  = (const float*)d_in[1];   // [M, N, C] f32
    float* codes = (float*)d_out;
    float* idx_o = (float*)d_out + (size_t)BB * MM * CC;
    const int write_idx = (out_size >= BB * MM * CC + BB * MM) ? 1 : 0;

    cudaFuncSetAttribute(fq_mma_kernel, cudaFuncAttributeMaxDynamicSharedMemorySize, SMEM_TOTAL);
    fq_mma_kernel<<<NBLK, 256, SMEM_TOTAL>>>(inp, cb, codes, idx_o, write_idx);
}